// round 1
// baseline (speedup 1.0000x reference)
#include <cuda_runtime.h>

// Problem constants (fixed shapes from the reference):
//   inputs: [B=4, C=8, H=256, W=256] f32  -> d_in[0], 2,097,152 elems
//   se_coef: scalar f32                    -> d_in[1], 1 elem
//   output: [B, C, S=4, H, W] f32          -> d_out, 8,388,608 elems
// Per scale k: t = 4^k, radius RAD = 4*2^k, penalty pen(x) = c * x^2 / (4t).
// Closing = Ev(Eh(Dv(Dh(x)))) per scale. Pads: -10000 (dilation) / +10000 (erosion),
// with the penalty applied to the pad value too (matches jnp.pad-then-subtract).

static constexpr int Wd = 256;
static constexpr int Hd = 256;
static constexpr int BCn = 32;   // B*C
static constexpr int Sn  = 4;

// Ping-pong scratch planes, [BC, S, H, W] layout (same as output layout).
__device__ float g_t1[(size_t)BCn * Sn * Hd * Wd];
__device__ float g_t2[(size_t)BCn * Sn * Hd * Wd];

// ---------------------------------------------------------------------------
// Horizontal pass. One CTA = 8 rows; one warp = one row; each thread computes
// 8 consecutive outputs. Padded row staged in smem, read back as float4.
// ISMAX=true: dilation, src = external input [BC,H,W], dst = g_t1.
// ISMAX=false: erosion, src = g_t2 [BC,S,H,W],       dst = g_t1.
// ---------------------------------------------------------------------------
template <int K, bool ISMAX>
__global__ void __launch_bounds__(256) hpass_kernel(const float* __restrict__ ext,
                                                    const float* __restrict__ cptr)
{
    constexpr int   RAD   = 4 << K;
    constexpr int   SP    = Wd + 2 * RAD;             // padded row pitch (mult of 4)
    constexpr float INV4T = 1.0f / (float)(1 << (2 * K + 2));
    constexpr float PADV  = ISMAX ? -10000.0f : 10000.0f;

    __shared__ float sbuf[8 * SP];

    const float c  = __ldg(cptr);
    const float pc = ISMAX ? -(c * INV4T) : (c * INV4T);

    const int row0 = blockIdx.x * 8;   // among BC*H = 8192 rows

    // ---- stage 8 padded rows into smem ----
    for (int i = threadIdx.x; i < 8 * SP; i += 256) {
        const int r  = i / SP;
        const int x  = i - r * SP;
        const int gr = row0 + r;
        const int bc = gr >> 8;
        const int h  = gr & 255;
        const int xin = x - RAD;
        float v = PADV;
        if ((unsigned)xin < (unsigned)Wd) {
            if constexpr (ISMAX) {
                v = ext[((size_t)bc * Hd + h) * Wd + xin];
            } else {
                v = g_t2[(((size_t)bc * Sn + K) * Hd + h) * Wd + xin];
            }
        }
        sbuf[i] = v;
    }
    __syncthreads();

    const int r = threadIdx.x >> 5;     // row within CTA (warp-per-row)
    const int q = threadIdx.x & 31;     // 8 outputs at x = 8q..8q+7
    const float* rb = &sbuf[r * SP + q * 8];

    float acc[8];
#pragma unroll
    for (int i = 0; i < 8; ++i) acc[i] = ISMAX ? -3.402823466e38f : 3.402823466e38f;

#pragma unroll
    for (int jc = 0; jc < (2 * RAD + 8) / 4; ++jc) {
        const float4 vv = *reinterpret_cast<const float4*>(rb + 4 * jc);
        const float va[4] = {vv.x, vv.y, vv.z, vv.w};
#pragma unroll
        for (int u = 0; u < 4; ++u) {
            const int jj = 4 * jc + u;
#pragma unroll
            for (int rr = 0; rr < 8; ++rr) {
                const int off = jj - rr - RAD;
                if (off >= -RAD && off <= RAD) {
                    const float t = fmaf(pc, (float)(off * off), va[u]);
                    acc[rr] = ISMAX ? fmaxf(acc[rr], t) : fminf(acc[rr], t);
                }
            }
        }
    }

    const int gr = row0 + r;
    const int bc = gr >> 8;
    const int h  = gr & 255;
    float* dp = g_t1 + (((size_t)bc * Sn + K) * Hd + h) * Wd + q * 8;
#pragma unroll
    for (int rr = 0; rr < 8; ++rr) dp[rr] = acc[rr];
}

// ---------------------------------------------------------------------------
// Vertical pass. One CTA = full 256-wide stripe x 8 output rows; thread = one
// column, streams the (2*RAD+8)-row window through registers with clamped LDG.
// ISMAX=true: dilation, src = g_t1, dst = g_t2.
// ISMAX=false: erosion, src = g_t1, dst = extdst (final output).
// ---------------------------------------------------------------------------
template <int K, bool ISMAX>
__global__ void __launch_bounds__(256) vpass_kernel(float* __restrict__ extdst,
                                                    const float* __restrict__ cptr)
{
    constexpr int   RAD   = 4 << K;
    constexpr float INV4T = 1.0f / (float)(1 << (2 * K + 2));
    constexpr float PADV  = ISMAX ? -10000.0f : 10000.0f;

    const float c  = __ldg(cptr);
    const float pc = ISMAX ? -(c * INV4T) : (c * INV4T);

    const int x  = threadIdx.x;
    const int r0 = blockIdx.x * 8;
    const int bc = blockIdx.y;

    const float* sp = g_t1 + (((size_t)bc * Sn + K) * Hd) * (size_t)Wd + x;

    float acc[8];
#pragma unroll
    for (int i = 0; i < 8; ++i) acc[i] = ISMAX ? -3.402823466e38f : 3.402823466e38f;

#pragma unroll
    for (int jj = 0; jj < 2 * RAD + 8; ++jj) {
        const int row = r0 + jj - RAD;
        float v = PADV;
        if ((unsigned)row < (unsigned)Hd) v = __ldg(sp + (size_t)row * Wd);
#pragma unroll
        for (int rr = 0; rr < 8; ++rr) {
            const int off = jj - rr - RAD;
            if (off >= -RAD && off <= RAD) {
                const float t = fmaf(pc, (float)(off * off), v);
                acc[rr] = ISMAX ? fmaxf(acc[rr], t) : fminf(acc[rr], t);
            }
        }
    }

    float* base;
    if constexpr (ISMAX) base = g_t2; else base = extdst;
    float* dp = base + (((size_t)bc * Sn + K) * Hd + r0) * Wd + x;
#pragma unroll
    for (int rr = 0; rr < 8; ++rr) dp[(size_t)rr * Wd] = acc[rr];
}

// ---------------------------------------------------------------------------
// Launch: 4 scales x (Dh, Dv, Eh, Ev). All graph-capturable, no allocations.
// ---------------------------------------------------------------------------
template <int K>
static void run_scale(const float* in, const float* cp, float* out)
{
    const dim3 hgrid(BCn * Hd / 8);        // 1024 CTAs
    const dim3 vgrid(Hd / 8, BCn);         // 32 x 32 CTAs
    hpass_kernel<K, true ><<<hgrid, 256>>>(in, cp);       // Dh: in   -> t1
    vpass_kernel<K, true ><<<vgrid, 256>>>(nullptr, cp);  // Dv: t1   -> t2
    hpass_kernel<K, false><<<hgrid, 256>>>(nullptr, cp);  // Eh: t2   -> t1
    vpass_kernel<K, false><<<vgrid, 256>>>(out, cp);      // Ev: t1   -> out
}

extern "C" void kernel_launch(void* const* d_in, const int* in_sizes, int n_in,
                              void* d_out, int out_size)
{
    const float* in = (const float*)d_in[0];
    const float* cp = (const float*)d_in[1];
    float* out = (float*)d_out;

    run_scale<0>(in, cp, out);
    run_scale<1>(in, cp, out);
    run_scale<2>(in, cp, out);
    run_scale<3>(in, cp, out);
}